// round 5
// baseline (speedup 1.0000x reference)
#include <cuda_runtime.h>
#include <math.h>

// ---------------- problem constants ----------------
#define T_      1024
#define H_      2048
#define I_      1024
#define E_      16
#define TWOI_   2048
#define G_      4
#define EPG_    4
#define TOPK_   4
#define NPAIR_  (T_*TOPK_)
#define ROUTED_SCALE_ 2.5f

// ---------------- device scratch (no allocations allowed) ----------------
__device__ float d_gu  [(size_t)NPAIR_*TWOI_];
__device__ float d_act [(size_t)NPAIR_*I_];
__device__ float d_yrt [(size_t)NPAIR_*H_];
__device__ float d_sgu [(size_t)T_*TWOI_];
__device__ float d_sact[(size_t)T_*I_];
__device__ float d_sy  [(size_t)T_*H_];
__device__ int   d_cnt [E_];
__device__ int   d_tok [E_*T_];
__device__ int   d_dst [E_*T_];
__device__ float d_wslot[NPAIR_];

// ---------------- small kernels ----------------
__global__ void zero_cnt_kernel() {
    if (threadIdx.x < E_) d_cnt[threadIdx.x] = 0;
}

// One block per token. 16 warps -> 16 expert logits (fp32 exact),
// thread 0 replicates the reference grouped top-k.
__global__ void router_kernel(const float* __restrict__ x,
                              const float* __restrict__ gate_w,
                              const float* __restrict__ e_bias) {
    int t = blockIdx.x;
    int warp = threadIdx.x >> 5;
    int lane = threadIdx.x & 31;
    const float* xr = x + (size_t)t * H_;
    const float* wr = gate_w + (size_t)warp * H_;
    float s = 0.f;
    for (int h = lane; h < H_; h += 32) s += xr[h] * wr[h];
    #pragma unroll
    for (int o = 16; o; o >>= 1) s += __shfl_xor_sync(0xFFFFFFFFu, s, o);
    __shared__ float logit[E_];
    if (lane == 0) logit[warp] = s;
    __syncthreads();
    if (threadIdx.x == 0) {
        float sc[E_], sb[E_];
        #pragma unroll
        for (int e = 0; e < E_; e++) {
            sc[e] = 1.f / (1.f + expf(-logit[e]));
            sb[e] = sc[e] + e_bias[e];
        }
        float gs[G_];
        #pragma unroll
        for (int g = 0; g < G_; g++) {
            float m1 = -INFINITY, m2 = -INFINITY;
            #pragma unroll
            for (int i = 0; i < EPG_; i++) {
                float v = sb[g*EPG_ + i];
                if (v > m1) { m2 = m1; m1 = v; }
                else if (v > m2) { m2 = v; }
            }
            gs[g] = m1 + m2;
        }
        int g1 = 0;
        for (int g = 1; g < G_; g++) if (gs[g] > gs[g1]) g1 = g;
        int g2 = -1;
        for (int g = 0; g < G_; g++) {
            if (g == g1) continue;
            if (g2 < 0 || gs[g] > gs[g2]) g2 = g;
        }
        float tmp[E_];
        #pragma unroll
        for (int e = 0; e < E_; e++) {
            int g = e / EPG_;
            tmp[e] = (g == g1 || g == g2) ? sb[e] : 0.f;
        }
        bool taken[E_];
        #pragma unroll
        for (int e = 0; e < E_; e++) taken[e] = false;
        int ids[TOPK_]; float wv[TOPK_]; float wsum = 0.f;
        #pragma unroll
        for (int k = 0; k < TOPK_; k++) {
            int bi = -1; float bv = -INFINITY;
            for (int e = 0; e < E_; e++) {
                if (!taken[e] && tmp[e] > bv) { bv = tmp[e]; bi = e; }
            }
            taken[bi] = true;
            ids[k] = bi;
            wv[k] = sc[bi];
            wsum += wv[k];
        }
        float inv = 1.f / wsum;
        #pragma unroll
        for (int k = 0; k < TOPK_; k++) {
            int e = ids[k];
            int pos = atomicAdd(&d_cnt[e], 1);
            d_tok[e*T_ + pos] = t;
            d_dst[e*T_ + pos] = t*TOPK_ + k;
            d_wslot[t*TOPK_ + k] = wv[k] * inv;
        }
    }
}

// ---------------- tf32 helpers ----------------
__device__ __forceinline__ unsigned f2tf32(float x) {
    unsigned y;
    asm("cvt.rna.tf32.f32 %0, %1;" : "=r"(y) : "f"(x));
    return y;
}

__device__ __forceinline__ void mma_tf32(float c[4], const unsigned a[4], const unsigned b[2]) {
    asm volatile(
        "mma.sync.aligned.m16n8k8.row.col.f32.tf32.tf32.f32 "
        "{%0,%1,%2,%3}, {%4,%5,%6,%7}, {%8,%9}, {%0,%1,%2,%3};"
        : "+f"(c[0]), "+f"(c[1]), "+f"(c[2]), "+f"(c[3])
        : "r"(a[0]), "r"(a[1]), "r"(a[2]), "r"(a[3]), "r"(b[0]), "r"(b[1]));
}

// ---------------- tensor-core TN GEMM (legacy mma.sync, tf32) ----------------
// C[M,N] = A[M,K] * B[N,K]^T.
// CTA tile 128x128, BK=16, 128 threads = 4 warps (2Mx2N), warp tile 64x64.
// Double-buffered smem [m][k] layout (row stride 20 words: STS.128 and
// fragment LDS both conflict-free), register prefetch of the next k-slab.
#define RS 20   // smem row stride in words

template<bool GATHER_A, bool SCATTER_C, bool EXPERT>
__global__ void __launch_bounds__(128, 2)
mma_gemm_tn(const float* __restrict__ Abase, int lda,
            const float* __restrict__ Bbase, int ldb, long strideB,
            float* __restrict__ Cbase, int ldc,
            int Mfixed, const int* __restrict__ counts,
            const int* __restrict__ gatherA,
            const int* __restrict__ scatterC,
            int K)
{
    const int e = EXPERT ? blockIdx.z : 0;
    const int M = EXPERT ? counts[e] : Mfixed;
    const int m0 = blockIdx.y * 128;
    if (m0 >= M) return;
    const int n0 = blockIdx.x * 128;
    const float* B = Bbase + (long)e * strideB;

    __shared__ unsigned As[2][128*RS];
    __shared__ unsigned Bs[2][128*RS];

    const int tid  = threadIdx.x;
    const int lane = tid & 31;
    const int warp = tid >> 5;
    const int wm   = warp >> 1;        // 0..1, 64 M-rows
    const int wn   = warp & 1;         // 0..1, 64 N-cols
    const int g    = lane >> 2;        // 0..7
    const int tg   = lane & 3;         // 0..3

    // staging: thread t owns row t (A and B), 16 k-values per slab
    const bool a_ok = (m0 + tid) < M;
    long arow = 0;
    if (a_ok) arow = GATHER_A ? (long)gatherA[e*T_ + m0 + tid] : (long)(m0 + tid);
    const float* Ag = Abase + arow * lda;
    const float* Bg = B + (long)(n0 + tid) * ldb;

    const int ntiles = K >> 4;

    float4 pa[4], pb[4];
    #pragma unroll
    for (int c = 0; c < 4; c++) {
        pa[c] = a_ok ? *(const float4*)(Ag + c*4) : make_float4(0.f,0.f,0.f,0.f);
        pb[c] = *(const float4*)(Bg + c*4);
    }

    float acc[4][8][4];
    #pragma unroll
    for (int mt = 0; mt < 4; mt++)
        #pragma unroll
        for (int nt = 0; nt < 8; nt++)
            #pragma unroll
            for (int i = 0; i < 4; i++) acc[mt][nt][i] = 0.f;

    for (int kt = 0; kt < ntiles; kt++) {
        const int buf = kt & 1;
        // store current slab (cvt at staging time), STS.128 conflict-free
        unsigned* as = &As[buf][tid*RS];
        unsigned* bs = &Bs[buf][tid*RS];
        #pragma unroll
        for (int c = 0; c < 4; c++) {
            uint4 va; va.x = f2tf32(pa[c].x); va.y = f2tf32(pa[c].y);
                      va.z = f2tf32(pa[c].z); va.w = f2tf32(pa[c].w);
            *(uint4*)(as + c*4) = va;
            uint4 vb; vb.x = f2tf32(pb[c].x); vb.y = f2tf32(pb[c].y);
                      vb.z = f2tf32(pb[c].z); vb.w = f2tf32(pb[c].w);
            *(uint4*)(bs + c*4) = vb;
        }
        // prefetch next slab into registers (latency hides under compute)
        if (kt + 1 < ntiles) {
            const float* ag = Ag + (kt+1)*16;
            const float* bg = Bg + (kt+1)*16;
            #pragma unroll
            for (int c = 0; c < 4; c++) {
                pa[c] = a_ok ? *(const float4*)(ag + c*4) : make_float4(0.f,0.f,0.f,0.f);
                pb[c] = *(const float4*)(bg + c*4);
            }
        }
        __syncthreads();

        const unsigned* a_s = As[buf];
        const unsigned* b_s = Bs[buf];
        #pragma unroll
        for (int ks = 0; ks < 16; ks += 8) {
            unsigned a[4][4], b[8][2];
            #pragma unroll
            for (int mt = 0; mt < 4; mt++) {
                int mr = wm*64 + mt*16 + g;
                a[mt][0] = a_s[(mr    )*RS + ks + tg    ];
                a[mt][1] = a_s[(mr + 8)*RS + ks + tg    ];
                a[mt][2] = a_s[(mr    )*RS + ks + tg + 4];
                a[mt][3] = a_s[(mr + 8)*RS + ks + tg + 4];
            }
            #pragma unroll
            for (int nt = 0; nt < 8; nt++) {
                int nr = wn*64 + nt*8 + g;
                b[nt][0] = b_s[nr*RS + ks + tg    ];
                b[nt][1] = b_s[nr*RS + ks + tg + 4];
            }
            #pragma unroll
            for (int mt = 0; mt < 4; mt++)
                #pragma unroll
                for (int nt = 0; nt < 8; nt++)
                    mma_tf32(acc[mt][nt], a[mt], b[nt]);
        }
        // no second sync needed: next iteration writes the other buffer, and
        // the following overwrite of this buffer is fenced by the next sync.
    }

    // epilogue: c0,c1 -> row g cols 2tg,2tg+1 ; c2,c3 -> row g+8
    #pragma unroll
    for (int mt = 0; mt < 4; mt++) {
        #pragma unroll
        for (int half = 0; half < 2; half++) {
            int lm = m0 + wm*64 + mt*16 + g + half*8;
            if (lm < M) {
                long crow = SCATTER_C ? (long)scatterC[e*T_ + lm] : (long)lm;
                float* Cp = Cbase + crow * ldc + n0 + wn*64 + 2*tg;
                #pragma unroll
                for (int nt = 0; nt < 8; nt++) {
                    float2 v;
                    v.x = acc[mt][nt][half*2 + 0];
                    v.y = acc[mt][nt][half*2 + 1];
                    *(float2*)(Cp + nt*8) = v;
                }
            }
        }
    }
}

// ---------------- silu-and-mul ----------------
__global__ void silu_shared_kernel() {
    int idx = blockIdx.x * blockDim.x + threadIdx.x;
    if (idx >= T_*I_/4) return;
    int row = idx / (I_/4);
    int j4  = (idx % (I_/4)) * 4;
    const float4 g = *(const float4*)&d_sgu[(size_t)row*TWOI_ + j4];
    const float4 u = *(const float4*)&d_sgu[(size_t)row*TWOI_ + I_ + j4];
    float4 r;
    r.x = (g.x / (1.f + expf(-g.x))) * u.x;
    r.y = (g.y / (1.f + expf(-g.y))) * u.y;
    r.z = (g.z / (1.f + expf(-g.z))) * u.z;
    r.w = (g.w / (1.f + expf(-g.w))) * u.w;
    *(float4*)&d_sact[(size_t)row*I_ + j4] = r;
}

__global__ void silu_routed_kernel() {
    int idx = blockIdx.x * blockDim.x + threadIdx.x;
    if (idx >= NPAIR_*I_/4) return;
    int slot = idx / (I_/4);
    int j4   = (idx % (I_/4)) * 4;
    const float4 g = *(const float4*)&d_gu[(size_t)slot*TWOI_ + j4];
    const float4 u = *(const float4*)&d_gu[(size_t)slot*TWOI_ + I_ + j4];
    float w = d_wslot[slot];
    float4 r;
    r.x = w * (g.x / (1.f + expf(-g.x))) * u.x;
    r.y = w * (g.y / (1.f + expf(-g.y))) * u.y;
    r.z = w * (g.z / (1.f + expf(-g.z))) * u.z;
    r.w = w * (g.w / (1.f + expf(-g.w))) * u.w;
    *(float4*)&d_act[(size_t)slot*I_ + j4] = r;
}

// ---------------- final combine ----------------
__global__ void reduce_kernel(float* __restrict__ out) {
    int idx = blockIdx.x * blockDim.x + threadIdx.x;
    if (idx >= T_*H_/4) return;
    int t  = idx / (H_/4);
    int h4 = (idx % (H_/4)) * 4;
    float4 s  = *(const float4*)&d_sy[(size_t)t*H_ + h4];
    float4 y0 = *(const float4*)&d_yrt[((size_t)t*TOPK_ + 0)*H_ + h4];
    float4 y1 = *(const float4*)&d_yrt[((size_t)t*TOPK_ + 1)*H_ + h4];
    float4 y2 = *(const float4*)&d_yrt[((size_t)t*TOPK_ + 2)*H_ + h4];
    float4 y3 = *(const float4*)&d_yrt[((size_t)t*TOPK_ + 3)*H_ + h4];
    float4 r;
    r.x = s.x + ROUTED_SCALE_ * (y0.x + y1.x + y2.x + y3.x);
    r.y = s.y + ROUTED_SCALE_ * (y0.y + y1.y + y2.y + y3.y);
    r.z = s.z + ROUTED_SCALE_ * (y0.z + y1.z + y2.z + y3.z);
    r.w = s.w + ROUTED_SCALE_ * (y0.w + y1.w + y2.w + y3.w);
    *(float4*)&out[(size_t)t*H_ + h4] = r;
}

// ---------------- launcher ----------------
extern "C" void kernel_launch(void* const* d_in, const int* in_sizes, int n_in,
                              void* d_out, int out_size) {
    const float* x        = (const float*)d_in[0];
    const float* gate_w   = (const float*)d_in[1];
    const float* e_bias   = (const float*)d_in[2];
    const float* w_gu     = (const float*)d_in[3];
    const float* w_dn     = (const float*)d_in[4];
    const float* s_wgu    = (const float*)d_in[5];
    const float* s_wdn    = (const float*)d_in[6];
    float* out = (float*)d_out;

    float *p_gu, *p_act, *p_yrt, *p_sgu, *p_sact, *p_sy;
    int *p_cnt, *p_tok, *p_dst;
    cudaGetSymbolAddress((void**)&p_gu,   d_gu);
    cudaGetSymbolAddress((void**)&p_act,  d_act);
    cudaGetSymbolAddress((void**)&p_yrt,  d_yrt);
    cudaGetSymbolAddress((void**)&p_sgu,  d_sgu);
    cudaGetSymbolAddress((void**)&p_sact, d_sact);
    cudaGetSymbolAddress((void**)&p_sy,   d_sy);
    cudaGetSymbolAddress((void**)&p_cnt,  d_cnt);
    cudaGetSymbolAddress((void**)&p_tok,  d_tok);
    cudaGetSymbolAddress((void**)&p_dst,  d_dst);

    // 1. reset expert counters
    zero_cnt_kernel<<<1, 32>>>();

    // 2. router + gather-list construction (fp32 exact)
    router_kernel<<<T_, 512>>>(x, gate_w, e_bias);

    // 3. shared expert gate_up: [T,H] x [2I,H]^T -> [T,2I]
    mma_gemm_tn<false,false,false><<<dim3(TWOI_/128, T_/128, 1), 128>>>(
        x, H_, s_wgu, H_, 0, p_sgu, TWOI_, T_, p_cnt, p_tok, p_dst, H_);

    // 4. shared silu*mul
    silu_shared_kernel<<<(T_*I_/4 + 255)/256, 256>>>();

    // 5. shared expert down: [T,I] x [H,I]^T -> [T,H]
    mma_gemm_tn<false,false,false><<<dim3(H_/128, T_/128, 1), 128>>>(
        p_sact, I_, s_wdn, I_, 0, p_sy, H_, T_, p_cnt, p_tok, p_dst, I_);

    // 6. routed gate_up: gather tokens per expert, scatter to pair slots
    mma_gemm_tn<true,true,true><<<dim3(TWOI_/128, T_/128, E_), 128>>>(
        x, H_, w_gu, H_, (long)TWOI_*H_, p_gu, TWOI_, 0, p_cnt, p_tok, p_dst, H_);

    // 7. routed silu*mul*weight
    silu_routed_kernel<<<(NPAIR_*I_/4 + 255)/256, 256>>>();

    // 8. routed down: gather act rows by slot, scatter outputs by slot
    mma_gemm_tn<true,true,true><<<dim3(H_/128, T_/128, E_), 128>>>(
        p_act, I_, w_dn, I_, (long)H_*I_, p_yrt, H_, 0, p_cnt, p_dst, p_dst, I_);

    // 9. combine
    reduce_kernel<<<(T_*H_/4 + 255)/256, 256>>>(out);
}

// round 6
// speedup vs baseline: 1.6343x; 1.6343x over previous
#include <cuda_runtime.h>
#include <cuda_fp16.h>
#include <math.h>

// ---------------- problem constants ----------------
#define T_      1024
#define H_      2048
#define I_      1024
#define E_      16
#define TWOI_   2048
#define G_      4
#define EPG_    4
#define TOPK_   4
#define NPAIR_  (T_*TOPK_)
#define ROUTED_SCALE_ 2.5f

// ---------------- device scratch (no allocations allowed) ----------------
__device__ float d_gu  [(size_t)NPAIR_*TWOI_];
__device__ float d_act [(size_t)NPAIR_*I_];
__device__ float d_yrt [(size_t)NPAIR_*H_];
__device__ float d_sgu [(size_t)T_*TWOI_];
__device__ float d_sact[(size_t)T_*I_];
__device__ float d_sy  [(size_t)T_*H_];
__device__ int   d_cnt [E_];
__device__ int   d_tok [E_*T_];
__device__ int   d_dst [E_*T_];
__device__ float d_wslot[NPAIR_];

// ---------------- small kernels ----------------
__global__ void zero_cnt_kernel() {
    if (threadIdx.x < E_) d_cnt[threadIdx.x] = 0;
}

// One block per token. 16 warps -> 16 expert logits (fp32 exact),
// thread 0 replicates the reference grouped top-k.
__global__ void router_kernel(const float* __restrict__ x,
                              const float* __restrict__ gate_w,
                              const float* __restrict__ e_bias) {
    int t = blockIdx.x;
    int warp = threadIdx.x >> 5;
    int lane = threadIdx.x & 31;
    const float* xr = x + (size_t)t * H_;
    const float* wr = gate_w + (size_t)warp * H_;
    float s = 0.f;
    for (int h = lane; h < H_; h += 32) s += xr[h] * wr[h];
    #pragma unroll
    for (int o = 16; o; o >>= 1) s += __shfl_xor_sync(0xFFFFFFFFu, s, o);
    __shared__ float logit[E_];
    if (lane == 0) logit[warp] = s;
    __syncthreads();
    if (threadIdx.x == 0) {
        float sc[E_], sb[E_];
        #pragma unroll
        for (int e = 0; e < E_; e++) {
            sc[e] = 1.f / (1.f + expf(-logit[e]));
            sb[e] = sc[e] + e_bias[e];
        }
        float gs[G_];
        #pragma unroll
        for (int g = 0; g < G_; g++) {
            float m1 = -INFINITY, m2 = -INFINITY;
            #pragma unroll
            for (int i = 0; i < EPG_; i++) {
                float v = sb[g*EPG_ + i];
                if (v > m1) { m2 = m1; m1 = v; }
                else if (v > m2) { m2 = v; }
            }
            gs[g] = m1 + m2;
        }
        int g1 = 0;
        for (int g = 1; g < G_; g++) if (gs[g] > gs[g1]) g1 = g;
        int g2 = -1;
        for (int g = 0; g < G_; g++) {
            if (g == g1) continue;
            if (g2 < 0 || gs[g] > gs[g2]) g2 = g;
        }
        float tmp[E_];
        #pragma unroll
        for (int e = 0; e < E_; e++) {
            int g = e / EPG_;
            tmp[e] = (g == g1 || g == g2) ? sb[e] : 0.f;
        }
        bool taken[E_];
        #pragma unroll
        for (int e = 0; e < E_; e++) taken[e] = false;
        int ids[TOPK_]; float wv[TOPK_]; float wsum = 0.f;
        #pragma unroll
        for (int k = 0; k < TOPK_; k++) {
            int bi = -1; float bv = -INFINITY;
            for (int e = 0; e < E_; e++) {
                if (!taken[e] && tmp[e] > bv) { bv = tmp[e]; bi = e; }
            }
            taken[bi] = true;
            ids[k] = bi;
            wv[k] = sc[bi];
            wsum += wv[k];
        }
        float inv = 1.f / wsum;
        #pragma unroll
        for (int k = 0; k < TOPK_; k++) {
            int e = ids[k];
            int pos = atomicAdd(&d_cnt[e], 1);
            d_tok[e*T_ + pos] = t;
            d_dst[e*T_ + pos] = t*TOPK_ + k;
            d_wslot[t*TOPK_ + k] = wv[k] * inv;
        }
    }
}

// ---------------- fp16 helpers ----------------
__device__ __forceinline__ unsigned pack_h2(float lo, float hi) {
    unsigned r;
    asm("cvt.rn.f16x2.f32 %0, %1, %2;" : "=r"(r) : "f"(hi), "f"(lo));
    return r;  // low half = lo (first k), high half = hi
}

__device__ __forceinline__ void mma_f16(float c[4], const unsigned a[4], const unsigned b[2]) {
    asm volatile(
        "mma.sync.aligned.m16n8k16.row.col.f32.f16.f16.f32 "
        "{%0,%1,%2,%3}, {%4,%5,%6,%7}, {%8,%9}, {%0,%1,%2,%3};"
        : "+f"(c[0]), "+f"(c[1]), "+f"(c[2]), "+f"(c[3])
        : "r"(a[0]), "r"(a[1]), "r"(a[2]), "r"(a[3]), "r"(b[0]), "r"(b[1]));
}

// ---------------- tensor-core TN GEMM (fp16 m16n8k16, fp32 accum) ----------------
// C[M,N] = A[M,K] * B[N,K]^T.
// CTA tile 128x128, BK=32 (16 half2 words/row), 256 threads = 8 warps (4Mx2N),
// warp tile 32x64. Double-buffered smem (row stride 20 words: staging STS.128
// and all fragment LDS conflict-free), register prefetch of next k-slab.
#define RS 20   // smem row stride in 32-bit words (each word = 2 halves)

template<bool GATHER_A, bool SCATTER_C, bool EXPERT>
__global__ void __launch_bounds__(256, 2)
mma_gemm_tn(const float* __restrict__ Abase, int lda,
            const float* __restrict__ Bbase, int ldb, long strideB,
            float* __restrict__ Cbase, int ldc,
            int Mfixed, const int* __restrict__ counts,
            const int* __restrict__ gatherA,
            const int* __restrict__ scatterC,
            int K)
{
    const int e = EXPERT ? blockIdx.z : 0;
    const int M = EXPERT ? counts[e] : Mfixed;
    const int m0 = blockIdx.y * 128;
    if (m0 >= M) return;
    const int n0 = blockIdx.x * 128;
    const float* B = Bbase + (long)e * strideB;

    __shared__ unsigned As[2][128*RS];
    __shared__ unsigned Bs[2][128*RS];

    const int tid  = threadIdx.x;
    const int lane = tid & 31;
    const int warp = tid >> 5;
    const int wm   = warp >> 1;        // 0..3, 32 M-rows each
    const int wn   = warp & 1;         // 0..1, 64 N-cols each
    const int g    = lane >> 2;        // 0..7
    const int tg   = lane & 3;         // 0..3

    // staging: thread t owns row (t>>1), k-half (t&1): 16 floats -> 8 words
    const int lrow = tid >> 1;
    const int kfl  = (tid & 1) * 16;   // float offset within 32-float slab
    const int kwd  = (tid & 1) * 8;    // word offset within 16-word row

    const bool a_ok = (m0 + lrow) < M;
    long arow = 0;
    if (a_ok) arow = GATHER_A ? (long)gatherA[e*T_ + m0 + lrow] : (long)(m0 + lrow);
    const float* Ag = Abase + arow * lda + kfl;
    const float* Bg = B + (long)(n0 + lrow) * ldb + kfl;

    const int ntiles = K >> 5;   // BK = 32

    // prefetch slab 0
    float4 pa[4], pb[4];
    #pragma unroll
    for (int c = 0; c < 4; c++) {
        pa[c] = a_ok ? *(const float4*)(Ag + c*4) : make_float4(0.f,0.f,0.f,0.f);
        pb[c] = *(const float4*)(Bg + c*4);
    }

    float acc[2][8][4];
    #pragma unroll
    for (int mt = 0; mt < 2; mt++)
        #pragma unroll
        for (int nt = 0; nt < 8; nt++)
            #pragma unroll
            for (int i = 0; i < 4; i++) acc[mt][nt][i] = 0.f;

    for (int kt = 0; kt < ntiles; kt++) {
        const int buf = kt & 1;
        // stage current slab: cvt fp32->fp16x2, two STS.128 per matrix
        unsigned* as = &As[buf][lrow*RS + kwd];
        unsigned* bs = &Bs[buf][lrow*RS + kwd];
        {
            uint4 w0, w1;
            w0.x = pack_h2(pa[0].x, pa[0].y); w0.y = pack_h2(pa[0].z, pa[0].w);
            w0.z = pack_h2(pa[1].x, pa[1].y); w0.w = pack_h2(pa[1].z, pa[1].w);
            w1.x = pack_h2(pa[2].x, pa[2].y); w1.y = pack_h2(pa[2].z, pa[2].w);
            w1.z = pack_h2(pa[3].x, pa[3].y); w1.w = pack_h2(pa[3].z, pa[3].w);
            *(uint4*)(as)     = w0;
            *(uint4*)(as + 4) = w1;
            w0.x = pack_h2(pb[0].x, pb[0].y); w0.y = pack_h2(pb[0].z, pb[0].w);
            w0.z = pack_h2(pb[1].x, pb[1].y); w0.w = pack_h2(pb[1].z, pb[1].w);
            w1.x = pack_h2(pb[2].x, pb[2].y); w1.y = pack_h2(pb[2].z, pb[2].w);
            w1.z = pack_h2(pb[3].x, pb[3].y); w1.w = pack_h2(pb[3].z, pb[3].w);
            *(uint4*)(bs)     = w0;
            *(uint4*)(bs + 4) = w1;
        }
        // prefetch next slab (latency hides under this tile's MMA work)
        if (kt + 1 < ntiles) {
            const float* ag = Ag + (kt+1)*32;
            const float* bg = Bg + (kt+1)*32;
            #pragma unroll
            for (int c = 0; c < 4; c++) {
                pa[c] = a_ok ? *(const float4*)(ag + c*4) : make_float4(0.f,0.f,0.f,0.f);
                pb[c] = *(const float4*)(bg + c*4);
            }
        }
        __syncthreads();
        // single sync per iter is safe: all warps passing this sync have
        // finished computing on the OTHER buffer (their previous iteration).

        const unsigned* a_s = As[buf];
        const unsigned* b_s = Bs[buf];
        #pragma unroll
        for (int ks = 0; ks < 2; ks++) {       // two k16 groups per BK=32
            const int kw = ks * 8;
            unsigned a[2][4], b[8][2];
            #pragma unroll
            for (int mt = 0; mt < 2; mt++) {
                int mr = wm*32 + mt*16 + g;
                a[mt][0] = a_s[(mr    )*RS + kw + tg    ];
                a[mt][1] = a_s[(mr + 8)*RS + kw + tg    ];
                a[mt][2] = a_s[(mr    )*RS + kw + tg + 4];
                a[mt][3] = a_s[(mr + 8)*RS + kw + tg + 4];
            }
            #pragma unroll
            for (int nt = 0; nt < 8; nt++) {
                int nr = wn*64 + nt*8 + g;
                b[nt][0] = b_s[nr*RS + kw + tg    ];
                b[nt][1] = b_s[nr*RS + kw + tg + 4];
            }
            #pragma unroll
            for (int mt = 0; mt < 2; mt++)
                #pragma unroll
                for (int nt = 0; nt < 8; nt++)
                    mma_f16(acc[mt][nt], a[mt], b[nt]);
        }
    }

    // epilogue: c0,c1 -> row g cols 2tg,2tg+1 ; c2,c3 -> row g+8
    #pragma unroll
    for (int mt = 0; mt < 2; mt++) {
        #pragma unroll
        for (int half = 0; half < 2; half++) {
            int lm = m0 + wm*32 + mt*16 + g + half*8;
            if (lm < M) {
                long crow = SCATTER_C ? (long)scatterC[e*T_ + lm] : (long)lm;
                float* Cp = Cbase + crow * ldc + n0 + wn*64 + 2*tg;
                #pragma unroll
                for (int nt = 0; nt < 8; nt++) {
                    float2 v;
                    v.x = acc[mt][nt][half*2 + 0];
                    v.y = acc[mt][nt][half*2 + 1];
                    *(float2*)(Cp + nt*8) = v;
                }
            }
        }
    }
}

// ---------------- silu-and-mul ----------------
__global__ void silu_shared_kernel() {
    int idx = blockIdx.x * blockDim.x + threadIdx.x;
    if (idx >= T_*I_/4) return;
    int row = idx / (I_/4);
    int j4  = (idx % (I_/4)) * 4;
    const float4 g = *(const float4*)&d_sgu[(size_t)row*TWOI_ + j4];
    const float4 u = *(const float4*)&d_sgu[(size_t)row*TWOI_ + I_ + j4];
    float4 r;
    r.x = (g.x / (1.f + expf(-g.x))) * u.x;
    r.y = (g.y / (1.f + expf(-g.y))) * u.y;
    r.z = (g.z / (1.f + expf(-g.z))) * u.z;
    r.w = (g.w / (1.f + expf(-g.w))) * u.w;
    *(float4*)&d_sact[(size_t)row*I_ + j4] = r;
}

__global__ void silu_routed_kernel() {
    int idx = blockIdx.x * blockDim.x + threadIdx.x;
    if (idx >= NPAIR_*I_/4) return;
    int slot = idx / (I_/4);
    int j4   = (idx % (I_/4)) * 4;
    const float4 g = *(const float4*)&d_gu[(size_t)slot*TWOI_ + j4];
    const float4 u = *(const float4*)&d_gu[(size_t)slot*TWOI_ + I_ + j4];
    float w = d_wslot[slot];
    float4 r;
    r.x = w * (g.x / (1.f + expf(-g.x))) * u.x;
    r.y = w * (g.y / (1.f + expf(-g.y))) * u.y;
    r.z = w * (g.z / (1.f + expf(-g.z))) * u.z;
    r.w = w * (g.w / (1.f + expf(-g.w))) * u.w;
    *(float4*)&d_act[(size_t)slot*I_ + j4] = r;
}

// ---------------- final combine ----------------
__global__ void reduce_kernel(float* __restrict__ out) {
    int idx = blockIdx.x * blockDim.x + threadIdx.x;
    if (idx >= T_*H_/4) return;
    int t  = idx / (H_/4);
    int h4 = (idx % (H_/4)) * 4;
    float4 s  = *(const float4*)&d_sy[(size_t)t*H_ + h4];
    float4 y0 = *(const float4*)&d_yrt[((size_t)t*TOPK_ + 0)*H_ + h4];
    float4 y1 = *(const float4*)&d_yrt[((size_t)t*TOPK_ + 1)*H_ + h4];
    float4 y2 = *(const float4*)&d_yrt[((size_t)t*TOPK_ + 2)*H_ + h4];
    float4 y3 = *(const float4*)&d_yrt[((size_t)t*TOPK_ + 3)*H_ + h4];
    float4 r;
    r.x = s.x + ROUTED_SCALE_ * (y0.x + y1.x + y2.x + y3.x);
    r.y = s.y + ROUTED_SCALE_ * (y0.y + y1.y + y2.y + y3.y);
    r.z = s.z + ROUTED_SCALE_ * (y0.z + y1.z + y2.z + y3.z);
    r.w = s.w + ROUTED_SCALE_ * (y0.w + y1.w + y2.w + y3.w);
    *(float4*)&out[(size_t)t*H_ + h4] = r;
}

// ---------------- launcher ----------------
extern "C" void kernel_launch(void* const* d_in, const int* in_sizes, int n_in,
                              void* d_out, int out_size) {
    const float* x        = (const float*)d_in[0];
    const float* gate_w   = (const float*)d_in[1];
    const float* e_bias   = (const float*)d_in[2];
    const float* w_gu     = (const float*)d_in[3];
    const float* w_dn     = (const float*)d_in[4];
    const float* s_wgu    = (const float*)d_in[5];
    const float* s_wdn    = (const float*)d_in[6];
    float* out = (float*)d_out;

    float *p_gu, *p_act, *p_yrt, *p_sgu, *p_sact, *p_sy;
    int *p_cnt, *p_tok, *p_dst;
    cudaGetSymbolAddress((void**)&p_gu,   d_gu);
    cudaGetSymbolAddress((void**)&p_act,  d_act);
    cudaGetSymbolAddress((void**)&p_yrt,  d_yrt);
    cudaGetSymbolAddress((void**)&p_sgu,  d_sgu);
    cudaGetSymbolAddress((void**)&p_sact, d_sact);
    cudaGetSymbolAddress((void**)&p_sy,   d_sy);
    cudaGetSymbolAddress((void**)&p_cnt,  d_cnt);
    cudaGetSymbolAddress((void**)&p_tok,  d_tok);
    cudaGetSymbolAddress((void**)&p_dst,  d_dst);

    // 1. reset expert counters
    zero_cnt_kernel<<<1, 32>>>();

    // 2. router + gather-list construction (fp32 exact)
    router_kernel<<<T_, 512>>>(x, gate_w, e_bias);

    // 3. shared expert gate_up: [T,H] x [2I,H]^T -> [T,2I]
    mma_gemm_tn<false,false,false><<<dim3(TWOI_/128, T_/128, 1), 256>>>(
        x, H_, s_wgu, H_, 0, p_sgu, TWOI_, T_, p_cnt, p_tok, p_dst, H_);

    // 4. shared silu*mul
    silu_shared_kernel<<<(T_*I_/4 + 255)/256, 256>>>();

    // 5. shared expert down: [T,I] x [H,I]^T -> [T,H]
    mma_gemm_tn<false,false,false><<<dim3(H_/128, T_/128, 1), 256>>>(
        p_sact, I_, s_wdn, I_, 0, p_sy, H_, T_, p_cnt, p_tok, p_dst, I_);

    // 6. routed gate_up: gather tokens per expert, scatter to pair slots
    mma_gemm_tn<true,true,true><<<dim3(TWOI_/128, T_/128, E_), 256>>>(
        x, H_, w_gu, H_, (long)TWOI_*H_, p_gu, TWOI_, 0, p_cnt, p_tok, p_dst, H_);

    // 7. routed silu*mul*weight
    silu_routed_kernel<<<(NPAIR_*I_/4 + 255)/256, 256>>>();

    // 8. routed down: gather act rows by slot, scatter outputs by slot
    mma_gemm_tn<true,true,true><<<dim3(H_/128, T_/128, E_), 256>>>(
        p_act, I_, w_dn, I_, (long)H_*I_, p_yrt, H_, 0, p_cnt, p_dst, p_dst, I_);

    // 9. combine
    reduce_kernel<<<(T_*H_/4 + 255)/256, 256>>>(out);
}

// round 7
// speedup vs baseline: 1.8430x; 1.1277x over previous
#include <cuda_runtime.h>
#include <cuda_fp16.h>
#include <math.h>

// ---------------- problem constants ----------------
#define T_      1024
#define H_      2048
#define I_      1024
#define E_      16
#define TWOI_   2048
#define G_      4
#define EPG_    4
#define TOPK_   4
#define NPAIR_  (T_*TOPK_)
#define RSCALE_ 2.5f

// ---------------- device scratch (no allocations allowed) ----------------
__device__ float d_act [(size_t)NPAIR_*I_];   // routed silu(g)*u*w (by slot t*4+k)
__device__ float d_sact[(size_t)T_*I_];       // shared silu(g)*u
__device__ int   d_cnt [E_];
__device__ int   d_tok [E_*T_];               // gather: token per expert entry
__device__ int   d_dst [E_*T_];               // slot (t*4+k) per expert entry
__device__ float d_wslot[NPAIR_];             // routing weight per slot

// ---------------- small kernels ----------------
__global__ void zero_cnt_kernel() {
    if (threadIdx.x < E_) d_cnt[threadIdx.x] = 0;
}

// One block per token; 16 warps -> 16 logits (fp32 exact); thread 0 replicates
// the reference grouped top-k bit-for-bit on fp32 scores.
__global__ void router_kernel(const float* __restrict__ x,
                              const float* __restrict__ gate_w,
                              const float* __restrict__ e_bias) {
    int t = blockIdx.x;
    int warp = threadIdx.x >> 5;
    int lane = threadIdx.x & 31;
    const float* xr = x + (size_t)t * H_;
    const float* wr = gate_w + (size_t)warp * H_;
    float s = 0.f;
    for (int h = lane; h < H_; h += 32) s += xr[h] * wr[h];
    #pragma unroll
    for (int o = 16; o; o >>= 1) s += __shfl_xor_sync(0xFFFFFFFFu, s, o);
    __shared__ float logit[E_];
    if (lane == 0) logit[warp] = s;
    __syncthreads();
    if (threadIdx.x == 0) {
        float sc[E_], sb[E_];
        #pragma unroll
        for (int e = 0; e < E_; e++) {
            sc[e] = 1.f / (1.f + expf(-logit[e]));
            sb[e] = sc[e] + e_bias[e];
        }
        float gs[G_];
        #pragma unroll
        for (int g = 0; g < G_; g++) {
            float m1 = -INFINITY, m2 = -INFINITY;
            #pragma unroll
            for (int i = 0; i < EPG_; i++) {
                float v = sb[g*EPG_ + i];
                if (v > m1) { m2 = m1; m1 = v; }
                else if (v > m2) { m2 = v; }
            }
            gs[g] = m1 + m2;
        }
        int g1 = 0;
        for (int g = 1; g < G_; g++) if (gs[g] > gs[g1]) g1 = g;
        int g2 = -1;
        for (int g = 0; g < G_; g++) {
            if (g == g1) continue;
            if (g2 < 0 || gs[g] > gs[g2]) g2 = g;
        }
        float tmp[E_];
        #pragma unroll
        for (int e = 0; e < E_; e++) {
            int g = e / EPG_;
            tmp[e] = (g == g1 || g == g2) ? sb[e] : 0.f;
        }
        bool taken[E_];
        #pragma unroll
        for (int e = 0; e < E_; e++) taken[e] = false;
        int ids[TOPK_]; float wv[TOPK_]; float wsum = 0.f;
        #pragma unroll
        for (int k = 0; k < TOPK_; k++) {
            int bi = -1; float bv = -INFINITY;
            for (int e = 0; e < E_; e++) {
                if (!taken[e] && tmp[e] > bv) { bv = tmp[e]; bi = e; }
            }
            taken[bi] = true;
            ids[k] = bi;
            wv[k] = sc[bi];
            wsum += wv[k];
        }
        float inv = 1.f / wsum;
        #pragma unroll
        for (int k = 0; k < TOPK_; k++) {
            int e = ids[k];
            int pos = atomicAdd(&d_cnt[e], 1);
            d_tok[e*T_ + pos] = t;
            d_dst[e*T_ + pos] = t*TOPK_ + k;
            d_wslot[t*TOPK_ + k] = wv[k] * inv;
        }
    }
}

// ---------------- mma / ldmatrix helpers ----------------
__device__ __forceinline__ unsigned pack_h2(float lo, float hi) {
    unsigned r;
    asm("cvt.rn.f16x2.f32 %0, %1, %2;" : "=r"(r) : "f"(hi), "f"(lo));
    return r;
}
__device__ __forceinline__ void mma_f16(float c[4], const unsigned a[4], const unsigned b[2]) {
    asm volatile(
        "mma.sync.aligned.m16n8k16.row.col.f32.f16.f16.f32 "
        "{%0,%1,%2,%3}, {%4,%5,%6,%7}, {%8,%9}, {%0,%1,%2,%3};"
        : "+f"(c[0]), "+f"(c[1]), "+f"(c[2]), "+f"(c[3])
        : "r"(a[0]), "r"(a[1]), "r"(a[2]), "r"(a[3]), "r"(b[0]), "r"(b[1]));
}
__device__ __forceinline__ void ldsm4(unsigned &r0, unsigned &r1, unsigned &r2, unsigned &r3,
                                      unsigned addr) {
    asm volatile("ldmatrix.sync.aligned.m8n8.x4.shared.b16 {%0,%1,%2,%3}, [%4];"
                 : "=r"(r0), "=r"(r1), "=r"(r2), "=r"(r3) : "r"(addr));
}
__device__ __forceinline__ float silu_mul(float g, float u) {
    return (g / (1.f + expf(-g))) * u;
}

#define RS 20   // smem row stride in 32-bit words (word = half2)

// ============ fused gate_up GEMM + silu*mul(*w_slot) ============
// A[M, K] (tokens) x interleaved gate/up weight rows -> act[?, I] tile of 64 cols.
// B smem row r (0..127): even -> gate col n0a+(r>>1), odd -> up col n0a+(r>>1).
// mma output col pair (2tg, 2tg+1) = (gate j, up j) in one thread -> local silu.
template<bool GATHER_A, bool SCATTER_C, bool EXPERT, bool WEIGHTED>
__global__ void __launch_bounds__(256, 2)
gu_silu_gemm(const float* __restrict__ Abase, int lda,
             const float* __restrict__ Wbase, long strideW,
             float* __restrict__ Cbase,
             int Mfixed, const int* __restrict__ counts,
             const int* __restrict__ gatherA,
             const int* __restrict__ scatterC,
             const float* __restrict__ wslot,
             int K)
{
    const int e = EXPERT ? blockIdx.z : 0;
    const int M = EXPERT ? counts[e] : Mfixed;
    const int m0 = blockIdx.y * 128;
    if (m0 >= M) return;
    const int n0a = blockIdx.x * 64;    // act column block
    const float* W = Wbase + (long)e * strideW;

    __shared__ unsigned As[2][128*RS];
    __shared__ unsigned Bs[2][128*RS];

    const int tid  = threadIdx.x;
    const int lane = tid & 31;
    const int warp = tid >> 5;
    const int wm   = warp >> 1;   // 0..3
    const int wn   = warp & 1;    // 0..1
    const int g    = lane >> 2;
    const int tg   = lane & 3;

    // staging: thread owns row lrow, k-half (tid&1)
    const int lrow = tid >> 1;
    const int kfl  = (tid & 1) * 16;
    const int kwd  = (tid & 1) * 8;

    const bool a_ok = (m0 + lrow) < M;
    long arow = 0;
    if (a_ok) arow = GATHER_A ? (long)gatherA[e*T_ + m0 + lrow] : (long)(m0 + lrow);
    const float* Ag = Abase + arow * lda + kfl;
    // interleaved gate/up weight row
    const long brow = (long)((lrow & 1) * I_ + n0a + (lrow >> 1));
    const float* Bg = W + brow * K + kfl;

    const int ntiles = K >> 5;

    float4 pa[4], pb[4];
    #pragma unroll
    for (int c = 0; c < 4; c++) {
        pa[c] = a_ok ? *(const float4*)(Ag + c*4) : make_float4(0.f,0.f,0.f,0.f);
        pb[c] = *(const float4*)(Bg + c*4);
    }

    float acc[2][8][4];
    #pragma unroll
    for (int mt = 0; mt < 2; mt++)
        #pragma unroll
        for (int nt = 0; nt < 8; nt++)
            #pragma unroll
            for (int i = 0; i < 4; i++) acc[mt][nt][i] = 0.f;

    // ldmatrix lane-address components
    const int ml = lane >> 3, rl = lane & 7;
    const int a_r = wm*32 + (ml & 1)*8 + rl;
    const int a_w = (ml >> 1) * 4;
    const int b_r = wn*64 + (ml >> 1)*8 + rl;
    const int b_w = (ml & 1) * 4;
    const unsigned aBuf[2] = { (unsigned)__cvta_generic_to_shared(As[0]),
                               (unsigned)__cvta_generic_to_shared(As[1]) };
    const unsigned bBuf[2] = { (unsigned)__cvta_generic_to_shared(Bs[0]),
                               (unsigned)__cvta_generic_to_shared(Bs[1]) };

    for (int kt = 0; kt < ntiles; kt++) {
        const int buf = kt & 1;
        unsigned* as = &As[buf][lrow*RS + kwd];
        unsigned* bs = &Bs[buf][lrow*RS + kwd];
        {
            uint4 w0, w1;
            w0.x = pack_h2(pa[0].x, pa[0].y); w0.y = pack_h2(pa[0].z, pa[0].w);
            w0.z = pack_h2(pa[1].x, pa[1].y); w0.w = pack_h2(pa[1].z, pa[1].w);
            w1.x = pack_h2(pa[2].x, pa[2].y); w1.y = pack_h2(pa[2].z, pa[2].w);
            w1.z = pack_h2(pa[3].x, pa[3].y); w1.w = pack_h2(pa[3].z, pa[3].w);
            *(uint4*)(as)     = w0;
            *(uint4*)(as + 4) = w1;
            w0.x = pack_h2(pb[0].x, pb[0].y); w0.y = pack_h2(pb[0].z, pb[0].w);
            w0.z = pack_h2(pb[1].x, pb[1].y); w0.w = pack_h2(pb[1].z, pb[1].w);
            w1.x = pack_h2(pb[2].x, pb[2].y); w1.y = pack_h2(pb[2].z, pb[2].w);
            w1.z = pack_h2(pb[3].x, pb[3].y); w1.w = pack_h2(pb[3].z, pb[3].w);
            *(uint4*)(bs)     = w0;
            *(uint4*)(bs + 4) = w1;
        }
        if (kt + 1 < ntiles) {
            const float* ag = Ag + (kt+1)*32;
            const float* bg = Bg + (kt+1)*32;
            #pragma unroll
            for (int c = 0; c < 4; c++) {
                pa[c] = a_ok ? *(const float4*)(ag + c*4) : make_float4(0.f,0.f,0.f,0.f);
                pb[c] = *(const float4*)(bg + c*4);
            }
        }
        __syncthreads();

        const unsigned ab = aBuf[buf];
        const unsigned bb = bBuf[buf];
        #pragma unroll
        for (int ks = 0; ks < 2; ks++) {
            const int kw = ks * 8;
            unsigned a[2][4], b[8][2];
            #pragma unroll
            for (int mt = 0; mt < 2; mt++)
                ldsm4(a[mt][0], a[mt][1], a[mt][2], a[mt][3],
                      ab + (unsigned)(((a_r + mt*16)*RS + kw + a_w) * 4));
            #pragma unroll
            for (int p = 0; p < 4; p++)
                ldsm4(b[2*p][0], b[2*p][1], b[2*p+1][0], b[2*p+1][1],
                      bb + (unsigned)(((b_r + p*16)*RS + kw + b_w) * 4));
            #pragma unroll
            for (int mt = 0; mt < 2; mt++)
                #pragma unroll
                for (int nt = 0; nt < 8; nt++)
                    mma_f16(acc[mt][nt], a[mt], b[nt]);
        }
    }

    // epilogue: col pair (2tg even, 2tg+1 odd) = (gate j, up j), j = n0a+wn*32+nt*4+tg
    #pragma unroll
    for (int mt = 0; mt < 2; mt++) {
        #pragma unroll
        for (int half = 0; half < 2; half++) {
            int lm = m0 + wm*32 + mt*16 + g + half*8;
            if (lm < M) {
                long crow = SCATTER_C ? (long)scatterC[e*T_ + lm] : (long)lm;
                float w = WEIGHTED ? wslot[crow] : 1.f;
                float* Cp = Cbase + crow * I_ + n0a + wn*32 + tg;
                #pragma unroll
                for (int nt = 0; nt < 8; nt++) {
                    float gv = acc[mt][nt][half*2 + 0];
                    float uv = acc[mt][nt][half*2 + 1];
                    Cp[nt*4] = w * silu_mul(gv, uv);
                }
            }
        }
    }
}

// ============ down GEMM, fused output combine ============
// C[M,H] = A[M,I] * Wdn[H,I]^T.
// ATOMIC=false: plain store to out rows (shared expert, initializes out).
// ATOMIC=true : atomicAdd(out[slot>>2], 2.5*val) (routed experts).
template<bool GATHER_A, bool EXPERT, bool ATOMIC>
__global__ void __launch_bounds__(256, 2)
down_gemm(const float* __restrict__ Abase, int lda,
          const float* __restrict__ Wbase, long strideW,
          float* __restrict__ Out,
          int Mfixed, const int* __restrict__ counts,
          const int* __restrict__ gatherA,
          int K)
{
    const int e = EXPERT ? blockIdx.z : 0;
    const int M = EXPERT ? counts[e] : Mfixed;
    const int m0 = blockIdx.y * 128;
    if (m0 >= M) return;
    const int n0 = blockIdx.x * 128;
    const float* W = Wbase + (long)e * strideW;

    __shared__ unsigned As[2][128*RS];
    __shared__ unsigned Bs[2][128*RS];

    const int tid  = threadIdx.x;
    const int lane = tid & 31;
    const int warp = tid >> 5;
    const int wm   = warp >> 1;
    const int wn   = warp & 1;
    const int g    = lane >> 2;
    const int tg   = lane & 3;

    const int lrow = tid >> 1;
    const int kfl  = (tid & 1) * 16;
    const int kwd  = (tid & 1) * 8;

    const bool a_ok = (m0 + lrow) < M;
    long arow = 0;
    if (a_ok) arow = GATHER_A ? (long)gatherA[e*T_ + m0 + lrow] : (long)(m0 + lrow);
    const float* Ag = Abase + arow * lda + kfl;
    const float* Bg = W + (long)(n0 + lrow) * K + kfl;

    const int ntiles = K >> 5;

    float4 pa[4], pb[4];
    #pragma unroll
    for (int c = 0; c < 4; c++) {
        pa[c] = a_ok ? *(const float4*)(Ag + c*4) : make_float4(0.f,0.f,0.f,0.f);
        pb[c] = *(const float4*)(Bg + c*4);
    }

    float acc[2][8][4];
    #pragma unroll
    for (int mt = 0; mt < 2; mt++)
        #pragma unroll
        for (int nt = 0; nt < 8; nt++)
            #pragma unroll
            for (int i = 0; i < 4; i++) acc[mt][nt][i] = 0.f;

    const int ml = lane >> 3, rl = lane & 7;
    const int a_r = wm*32 + (ml & 1)*8 + rl;
    const int a_w = (ml >> 1) * 4;
    const int b_r = wn*64 + (ml >> 1)*8 + rl;
    const int b_w = (ml & 1) * 4;
    const unsigned aBuf[2] = { (unsigned)__cvta_generic_to_shared(As[0]),
                               (unsigned)__cvta_generic_to_shared(As[1]) };
    const unsigned bBuf[2] = { (unsigned)__cvta_generic_to_shared(Bs[0]),
                               (unsigned)__cvta_generic_to_shared(Bs[1]) };

    for (int kt = 0; kt < ntiles; kt++) {
        const int buf = kt & 1;
        unsigned* as = &As[buf][lrow*RS + kwd];
        unsigned* bs = &Bs[buf][lrow*RS + kwd];
        {
            uint4 w0, w1;
            w0.x = pack_h2(pa[0].x, pa[0].y); w0.y = pack_h2(pa[0].z, pa[0].w);
            w0.z = pack_h2(pa[1].x, pa[1].y); w0.w = pack_h2(pa[1].z, pa[1].w);
            w1.x = pack_h2(pa[2].x, pa[2].y); w1.y = pack_h2(pa[2].z, pa[2].w);
            w1.z = pack_h2(pa[3].x, pa[3].y); w1.w = pack_h2(pa[3].z, pa[3].w);
            *(uint4*)(as)     = w0;
            *(uint4*)(as + 4) = w1;
            w0.x = pack_h2(pb[0].x, pb[0].y); w0.y = pack_h2(pb[0].z, pb[0].w);
            w0.z = pack_h2(pb[1].x, pb[1].y); w0.w = pack_h2(pb[1].z, pb[1].w);
            w1.x = pack_h2(pb[2].x, pb[2].y); w1.y = pack_h2(pb[2].z, pb[2].w);
            w1.z = pack_h2(pb[3].x, pb[3].y); w1.w = pack_h2(pb[3].z, pb[3].w);
            *(uint4*)(bs)     = w0;
            *(uint4*)(bs + 4) = w1;
        }
        if (kt + 1 < ntiles) {
            const float* ag = Ag + (kt+1)*32;
            const float* bg = Bg + (kt+1)*32;
            #pragma unroll
            for (int c = 0; c < 4; c++) {
                pa[c] = a_ok ? *(const float4*)(ag + c*4) : make_float4(0.f,0.f,0.f,0.f);
                pb[c] = *(const float4*)(bg + c*4);
            }
        }
        __syncthreads();

        const unsigned ab = aBuf[buf];
        const unsigned bb = bBuf[buf];
        #pragma unroll
        for (int ks = 0; ks < 2; ks++) {
            const int kw = ks * 8;
            unsigned a[2][4], b[8][2];
            #pragma unroll
            for (int mt = 0; mt < 2; mt++)
                ldsm4(a[mt][0], a[mt][1], a[mt][2], a[mt][3],
                      ab + (unsigned)(((a_r + mt*16)*RS + kw + a_w) * 4));
            #pragma unroll
            for (int p = 0; p < 4; p++)
                ldsm4(b[2*p][0], b[2*p][1], b[2*p+1][0], b[2*p+1][1],
                      bb + (unsigned)(((b_r + p*16)*RS + kw + b_w) * 4));
            #pragma unroll
            for (int mt = 0; mt < 2; mt++)
                #pragma unroll
                for (int nt = 0; nt < 8; nt++)
                    mma_f16(acc[mt][nt], a[mt], b[nt]);
        }
    }

    #pragma unroll
    for (int mt = 0; mt < 2; mt++) {
        #pragma unroll
        for (int half = 0; half < 2; half++) {
            int lm = m0 + wm*32 + mt*16 + g + half*8;
            if (lm < M) {
                if (ATOMIC) {
                    int slot = gatherA[e*T_ + lm];
                    float* Cp = Out + (long)(slot >> 2) * H_ + n0 + wn*64 + 2*tg;
                    #pragma unroll
                    for (int nt = 0; nt < 8; nt++) {
                        atomicAdd(Cp + nt*8,     RSCALE_ * acc[mt][nt][half*2 + 0]);
                        atomicAdd(Cp + nt*8 + 1, RSCALE_ * acc[mt][nt][half*2 + 1]);
                    }
                } else {
                    float* Cp = Out + (long)lm * H_ + n0 + wn*64 + 2*tg;
                    #pragma unroll
                    for (int nt = 0; nt < 8; nt++) {
                        float2 v;
                        v.x = acc[mt][nt][half*2 + 0];
                        v.y = acc[mt][nt][half*2 + 1];
                        *(float2*)(Cp + nt*8) = v;
                    }
                }
            }
        }
    }
}

// ---------------- launcher ----------------
extern "C" void kernel_launch(void* const* d_in, const int* in_sizes, int n_in,
                              void* d_out, int out_size) {
    const float* x        = (const float*)d_in[0];
    const float* gate_w   = (const float*)d_in[1];
    const float* e_bias   = (const float*)d_in[2];
    const float* w_gu     = (const float*)d_in[3];
    const float* w_dn     = (const float*)d_in[4];
    const float* s_wgu    = (const float*)d_in[5];
    const float* s_wdn    = (const float*)d_in[6];
    float* out = (float*)d_out;

    float *p_act, *p_sact, *p_wslot;
    int *p_cnt, *p_tok, *p_dst;
    cudaGetSymbolAddress((void**)&p_act,   d_act);
    cudaGetSymbolAddress((void**)&p_sact,  d_sact);
    cudaGetSymbolAddress((void**)&p_wslot, d_wslot);
    cudaGetSymbolAddress((void**)&p_cnt,   d_cnt);
    cudaGetSymbolAddress((void**)&p_tok,   d_tok);
    cudaGetSymbolAddress((void**)&p_dst,   d_dst);

    // 1. reset expert counters
    zero_cnt_kernel<<<1, 32>>>();

    // 2. router + gather-list construction (fp32 exact)
    router_kernel<<<T_, 512>>>(x, gate_w, e_bias);

    // 3. shared gate_up + silu (fused): x[T,H] x interleaved s_wgu -> d_sact[T,I]
    gu_silu_gemm<false,false,false,false><<<dim3(I_/64, T_/128, 1), 256>>>(
        x, H_, s_wgu, 0, p_sact, T_, p_cnt, p_tok, p_dst, p_wslot, H_);

    // 4. shared down: d_sact x s_wdn^T -> out (plain store, initializes out)
    down_gemm<false,false,false><<<dim3(H_/128, T_/128, 1), 256>>>(
        p_sact, I_, s_wdn, 0, out, T_, p_cnt, p_dst, I_);

    // 5. routed gate_up + silu + w_slot (fused): gather tokens, scatter to slots
    gu_silu_gemm<true,true,true,true><<<dim3(I_/64, T_/128, E_), 256>>>(
        x, H_, w_gu, (long)TWOI_*H_, p_act, 0, p_cnt, p_tok, p_dst, p_wslot, H_);

    // 6. routed down: gather act by slot, atomicAdd 2.5*y into out[slot>>2]
    down_gemm<true,true,true><<<dim3(H_/128, T_/128, E_), 256>>>(
        p_act, I_, w_dn, (long)H_*I_, out, 0, p_cnt, p_dst, I_);
}